// round 11
// baseline (speedup 1.0000x reference)
#include <cuda_runtime.h>
#include <cuda_bf16.h>

#define NT 256
typedef unsigned long long u64;

// X=Y=4, D=6, F_IN=2, F_OUT=10, CX=CY=2, B=1024
// inputs: (1024,4,4,2)  peps: (4,4,2,6,6,6,6)  peps_center: (2,10,6,6,6,6)
// out: (1024,10) float32
//
// All _unit() normalizations are positive per-batch scalars feeding a
// multilinear network -> they cancel under the final row-normalization.
// Keep 3 (row0 env, env_top, env_bot) purely as fp32 range-keepers, plus
// max-scaling of the final 10-vector.

// ---------------- f32x2 packed-math helpers (FFMA2 path) ----------------
static __device__ __forceinline__ u64 pk2(float a, float b) {
    u64 r; asm("mov.b64 %0,{%1,%2};" : "=l"(r) : "f"(a), "f"(b)); return r;
}
static __device__ __forceinline__ void fma2(u64& d, u64 a, u64 b) {
    asm("fma.rn.f32x2 %0,%1,%2,%0;" : "+l"(d) : "l"(a), "l"(b));
}

// ---- node arena offsets (floats) ----
#define N00 0       // 36   (r,d)
#define N01 36      // 216  (r,d,l)
#define N02 252     // 216
#define N03 468     // 36   (d,l)
#define N10 504     // 216  (u,r,d)
#define N11 720     // 1296 TT layout [u][a][x][r]
#define N12 2016    // 1296 TT
#define N13 3312    // 216  (u,d,l)
#define N30 3528    // 36   (u,r)
#define N31 3564    // 216  (u,r,l)
#define N32 3780    // 216
#define N33 3996    // 36   (u,l)
#define N20 4032    // 216  (u,r,d)
#define N21 4248    // 1296 TT
#define N23 5544    // 216  (u,d,l)
#define NODES_TOTAL 5760

struct Smem {
    float Sa[7776];
    float Sb[7776];
    float nodes[NODES_TOTAL];
    float envtop[1296];
    float envbot[1296];
    float red[8];
    float dots[20];
};

// ---------------- block reduction (sum) ----------------
__device__ __forceinline__ float block_reduce(float v, float* red) {
    #pragma unroll
    for (int o = 16; o; o >>= 1) v += __shfl_xor_sync(0xffffffffu, v, o);
    int w = threadIdx.x >> 5;
    if ((threadIdx.x & 31) == 0) red[w] = v;
    __syncthreads();
    float r;
    if (threadIdx.x < 32) {
        r = (threadIdx.x < 8) ? red[threadIdx.x] : 0.f;
        #pragma unroll
        for (int o = 4; o; o >>= 1) r += __shfl_xor_sync(0xffffffffu, r, o);
        if (threadIdx.x == 0) red[0] = r;
    }
    __syncthreads();
    r = red[0];
    __syncthreads();
    return r;
}

__device__ __forceinline__ void normalize1296(float* buf, float* red) {
    float4* b4 = reinterpret_cast<float4*>(buf);
    float ss = 0.f;
    for (int i = threadIdx.x; i < 324; i += NT) {
        float4 v = b4[i];
        ss += v.x * v.x + v.y * v.y + v.z * v.z + v.w * v.w;
    }
    ss = block_reduce(ss, red);
    float inv = rsqrtf(ss);
    for (int i = threadIdx.x; i < 324; i += NT) {
        float4 v = b4[i];
        b4[i] = make_float4(v.x * inv, v.y * inv, v.z * inv, v.w * inv);
    }
    __syncthreads();
}

// ---------------- node fills ----------------
template <int I, int J, int U, int R, int Dd, int L>
__device__ __forceinline__ void fill_node(float* __restrict__ buf,
                                          const float* __restrict__ peps,
                                          const float* __restrict__ xs) {
    const float x0 = xs[(I * 4 + J) * 2 + 0];
    const float x1 = xs[(I * 4 + J) * 2 + 1];
    const float* T0 = peps + (size_t)((I * 4 + J) * 2) * 1296;
    const float* T1 = T0 + 1296;
    constexpr int n = U * R * Dd * L;
    for (int idx = threadIdx.x; idx < n; idx += NT) {
        int l = idx % L;
        int t = idx / L;
        int d = t % Dd; t /= Dd;
        int r = t % R;
        int u = t / R;
        int g = ((u * 6 + r) * 6 + d) * 6 + l;
        buf[idx] = fmaf(x0, __ldg(T0 + g), x1 * __ldg(T1 + g));
    }
}

// full node in transposed layout TT[u*216 + d*36 + l*6 + r] = Node[u][r][d][l]
template <int I, int J>
__device__ __forceinline__ void fill_node_tt(float* __restrict__ buf,
                                             const float* __restrict__ peps,
                                             const float* __restrict__ xs) {
    const float x0 = xs[(I * 4 + J) * 2 + 0];
    const float x1 = xs[(I * 4 + J) * 2 + 1];
    const float* T0 = peps + (size_t)((I * 4 + J) * 2) * 1296;
    const float* T1 = T0 + 1296;
    for (int g = threadIdx.x; g < 1296; g += NT) {   // g linear: coalesced LDG
        int l = g % 6, d = (g / 6) % 6, r = (g / 36) % 6, u = g / 216;
        buf[u * 216 + d * 36 + l * 6 + r] = fmaf(x0, __ldg(T0 + g), x1 * __ldg(T1 + g));
    }
}

// ---------------- specialized contraction steps (no div/mod in loops) ------

// M=6, U=1: out[t] = sum_x Sin[m*6+x] * T[a*SA + r*SR + x], t=m*36+a*6+r
template <int SA, int SR>
__device__ __forceinline__ void step6(const float* __restrict__ Sin,
                                      float* __restrict__ Sout,
                                      const float* __restrict__ T) {
    const int t = threadIdx.x;
    if (t < 216) {
        const int m = t / 36, a = (t / 6) % 6, r = t % 6;
        const float* sp = Sin + m * 6;
        const float* tp = T + a * SA + r * SR;
        float acc = 0.f;
        #pragma unroll
        for (int x = 0; x < 6; ++x) acc = fmaf(sp[x], tp[x], acc);
        Sout[t] = acc;
    }
    __syncthreads();
}

// M=36, U=1: thread=(m,a) computes 6 r. out base = t*6.
template <int SA, int SR>
__device__ __forceinline__ void step36(const float* __restrict__ Sin,
                                       float* __restrict__ Sout,
                                       const float* __restrict__ T) {
    const int t = threadIdx.x;
    if (t < 216) {
        const int m = t / 6, a = t % 6;
        float sv[6];
        const float2* sp = reinterpret_cast<const float2*>(Sin + m * 6);
        #pragma unroll
        for (int q = 0; q < 3; ++q) { float2 v = sp[q]; sv[q*2] = v.x; sv[q*2+1] = v.y; }
        float acc[6];
        #pragma unroll
        for (int r = 0; r < 6; ++r) {
            const float2* tp = reinterpret_cast<const float2*>(T + a * SA + r * SR);
            float tv[6];
            #pragma unroll
            for (int q = 0; q < 3; ++q) { float2 v = tp[q]; tv[q*2] = v.x; tv[q*2+1] = v.y; }
            float s = 0.f;
            #pragma unroll
            for (int x = 0; x < 6; ++x) s = fmaf(sv[x], tv[x], s);
            acc[r] = s;
        }
        float2* op = reinterpret_cast<float2*>(Sout + t * 6);
        #pragma unroll
        for (int q = 0; q < 3; ++q) op[q] = make_float2(acc[q*2], acc[q*2+1]);
    }
    __syncthreads();
}

// M=216, X=6, R=1, U=1: out[m*6+a] = sum_x Sin[m*6+x]*T[a*6+x]
__device__ __forceinline__ void stepX6R1(const float* __restrict__ Sin,
                                         float* __restrict__ Sout,
                                         const float* __restrict__ T) {
    const int m = threadIdx.x;
    if (m < 216) {
        float sv[6];
        const float2* sp = reinterpret_cast<const float2*>(Sin + m * 6);
        #pragma unroll
        for (int q = 0; q < 3; ++q) { float2 v = sp[q]; sv[q*2] = v.x; sv[q*2+1] = v.y; }
        float tt[36];
        const float4* p = reinterpret_cast<const float4*>(T);
        #pragma unroll
        for (int q = 0; q < 9; ++q) { float4 v = p[q]; tt[q*4]=v.x; tt[q*4+1]=v.y; tt[q*4+2]=v.z; tt[q*4+3]=v.w; }
        float acc[6];
        #pragma unroll
        for (int a = 0; a < 6; ++a) {
            float s = 0.f;
            #pragma unroll
            for (int x = 0; x < 6; ++x) s = fmaf(sv[x], tt[a*6+x], s);
            acc[a] = s;
        }
        float2* op = reinterpret_cast<float2*>(Sout + m * 6);
        #pragma unroll
        for (int q = 0; q < 3; ++q) op[q] = make_float2(acc[q*2], acc[q*2+1]);
    }
    __syncthreads();
}

// X=1 "insert new row" (N10/N20): out[m*36+a*6+r] = sum_u Sin[u*216+m]*T[u*36+r*6+a]
__device__ __forceinline__ void insert_step(const float* __restrict__ Sin,
                                            float* __restrict__ Sout,
                                            const float* __restrict__ T) {
    const int m = threadIdx.x;
    if (m < 216) {
        float acc[36];
        #pragma unroll
        for (int i = 0; i < 36; ++i) acc[i] = 0.f;
        #pragma unroll
        for (int u = 0; u < 6; ++u) {
            const float s = Sin[u * 216 + m];
            float tt[36];
            const float4* p = reinterpret_cast<const float4*>(T + u * 36);  // broadcast
            #pragma unroll
            for (int q = 0; q < 9; ++q) { float4 v = p[q]; tt[q*4]=v.x; tt[q*4+1]=v.y; tt[q*4+2]=v.z; tt[q*4+3]=v.w; }
            #pragma unroll
            for (int a = 0; a < 6; ++a)
                #pragma unroll
                for (int r = 0; r < 6; ++r)
                    acc[a * 6 + r] = fmaf(s, tt[r * 6 + a], acc[a * 6 + r]);
        }
        float4* op = reinterpret_cast<float4*>(Sout + m * 36);
        #pragma unroll
        for (int q = 0; q < 9; ++q) op[q] = make_float4(acc[q*4], acc[q*4+1], acc[q*4+2], acc[q*4+3]);
    }
    __syncthreads();
}

// N13-type: out[m*6+a] = sum_{u,x} Sin[(u*216+m)*6+x] * T[u*36+a*6+x]
__device__ __forceinline__ void contract_u_step(const float* __restrict__ Sin,
                                                float* __restrict__ Sout,
                                                const float* __restrict__ T) {
    const int m = threadIdx.x;
    if (m < 216) {
        float acc[6] = {0.f, 0.f, 0.f, 0.f, 0.f, 0.f};
        #pragma unroll
        for (int u = 0; u < 6; ++u) {
            float sv[6];
            const float2* sp = reinterpret_cast<const float2*>(Sin + (u * 216 + m) * 6);
            #pragma unroll
            for (int q = 0; q < 3; ++q) { float2 v = sp[q]; sv[q*2] = v.x; sv[q*2+1] = v.y; }
            float tt[36];
            const float4* p = reinterpret_cast<const float4*>(T + u * 36);  // broadcast
            #pragma unroll
            for (int q = 0; q < 9; ++q) { float4 v = p[q]; tt[q*4]=v.x; tt[q*4+1]=v.y; tt[q*4+2]=v.z; tt[q*4+3]=v.w; }
            #pragma unroll
            for (int a = 0; a < 6; ++a) {
                float s = acc[a];
                #pragma unroll
                for (int x = 0; x < 6; ++x) s = fmaf(sv[x], tt[a*6+x], s);
                acc[a] = s;
            }
        }
        float2* op = reinterpret_cast<float2*>(Sout + m * 6);
        #pragma unroll
        for (int q = 0; q < 3; ++q) op[q] = make_float2(acc[q*2], acc[q*2+1]);
    }
    __syncthreads();
}

// ---------------- hot step with TT node + FFMA2 (r packed), 128-bit LDS ----
// out[mg*216 + mi*36 + a*6 + r] = sum_{u,x} Sin[u*1296+(mg*6+mi)*6+x] * TT[u*216+a*36+x*6+r]
__device__ __forceinline__ void cstep_full_tt(const float* __restrict__ Sin,
                                              float* __restrict__ Sout,
                                              const float* __restrict__ TT) {
    const int t = threadIdx.x;
    if (t < 216) {
        const int mg = t / 6, a = t % 6;
        u64 acc[18];
        #pragma unroll
        for (int i = 0; i < 18; ++i) acc[i] = 0ull;
        #pragma unroll
        for (int u = 0; u < 6; ++u) {
            // TT block: 36 floats = 18 u64, loaded as 9 LDS.128
            u64 tt2[18];
            const ulonglong2* tp = reinterpret_cast<const ulonglong2*>(TT + u * 216 + a * 36);
            #pragma unroll
            for (int q = 0; q < 9; ++q) { ulonglong2 v = tp[q]; tt2[q*2] = v.x; tt2[q*2+1] = v.y; }
            // sv loaded per mi-pair: 12 floats = 3 LDS.128 (16B aligned, mi even)
            const float4* sp4 = reinterpret_cast<const float4*>(Sin + u * 1296 + mg * 36);
            #pragma unroll
            for (int mip = 0; mip < 3; ++mip) {
                float sv[12];
                #pragma unroll
                for (int q = 0; q < 3; ++q) {
                    float4 v = sp4[mip * 3 + q];
                    sv[q*4] = v.x; sv[q*4+1] = v.y; sv[q*4+2] = v.z; sv[q*4+3] = v.w;
                }
                #pragma unroll
                for (int mi2 = 0; mi2 < 2; ++mi2) {
                    const int mi = mip * 2 + mi2;
                    #pragma unroll
                    for (int x = 0; x < 6; ++x) {
                        const float s = sv[mi2 * 6 + x];
                        const u64 s2 = pk2(s, s);
                        #pragma unroll
                        for (int rp = 0; rp < 3; ++rp) fma2(acc[mi*3+rp], s2, tt2[x*3+rp]);
                    }
                }
            }
        }
        float* ob = Sout + mg * 216 + a * 6;
        #pragma unroll
        for (int mi = 0; mi < 6; ++mi) {
            u64* op = reinterpret_cast<u64*>(ob + mi * 36);
            #pragma unroll
            for (int rp = 0; rp < 3; ++rp) op[rp] = acc[mi*3+rp];
        }
    }
    __syncthreads();
}

__global__ void __launch_bounds__(NT, 2)
peps_kernel(const float* __restrict__ inp, const float* __restrict__ peps,
            const float* __restrict__ pc, float* __restrict__ out) {
    extern __shared__ __align__(16) char smem_raw[];
    Smem& S = *reinterpret_cast<Smem*>(smem_raw);
    const int b = blockIdx.x;
    const float* xs = inp + b * 32;
    float* nd = S.nodes;

    // ============ Phase 1: build all 15 node tensors (one barrier) ============
    fill_node<0, 0, 1, 6, 6, 1>(nd + N00, peps, xs);
    fill_node<0, 1, 1, 6, 6, 6>(nd + N01, peps, xs);
    fill_node<0, 2, 1, 6, 6, 6>(nd + N02, peps, xs);
    fill_node<0, 3, 1, 1, 6, 6>(nd + N03, peps, xs);
    fill_node<1, 0, 6, 6, 6, 1>(nd + N10, peps, xs);
    fill_node_tt<1, 1>(nd + N11, peps, xs);
    fill_node_tt<1, 2>(nd + N12, peps, xs);
    fill_node<1, 3, 6, 1, 6, 6>(nd + N13, peps, xs);
    fill_node<3, 0, 6, 6, 1, 1>(nd + N30, peps, xs);
    fill_node<3, 1, 6, 6, 1, 6>(nd + N31, peps, xs);
    fill_node<3, 2, 6, 6, 1, 6>(nd + N32, peps, xs);
    fill_node<3, 3, 6, 1, 1, 6>(nd + N33, peps, xs);
    fill_node<2, 0, 6, 6, 6, 1>(nd + N20, peps, xs);
    fill_node_tt<2, 1>(nd + N21, peps, xs);
    fill_node<2, 3, 6, 1, 6, 6>(nd + N23, peps, xs);
    __syncthreads();

    // ============ Row 0 (top boundary) ============
    if (threadIdx.x < 36) {
        int d = threadIdx.x / 6, r = threadIdx.x % 6;
        S.Sa[d * 6 + r] = nd[N00 + r * 6 + d];
    }
    __syncthreads();
    step6<6, 36>(S.Sa, S.Sb, nd + N01);       // -> 216
    step36<6, 36>(S.Sb, S.Sa, nd + N02);      // -> 1296
    stepX6R1(S.Sa, S.Sb, nd + N03);           // -> 1296
    normalize1296(S.Sb, S.red);               // range-keeper

    // ============ Row 1 ============
    insert_step(S.Sb, S.Sa, nd + N10);        // -> 7776
    cstep_full_tt(S.Sa, S.Sb, nd + N11);      // -> 7776
    cstep_full_tt(S.Sb, S.Sa, nd + N12);      // -> 7776
    contract_u_step(S.Sa, S.envtop, nd + N13);// env_top 1296
    normalize1296(S.envtop, S.red);           // range-keeper

    // ============ Row 3 (bottom boundary) ============
    for (int i = threadIdx.x; i < 36; i += NT) S.Sa[i] = nd[N30 + i];
    __syncthreads();
    step6<36, 6>(S.Sa, S.Sb, nd + N31);       // -> 216
    step36<36, 6>(S.Sb, S.Sa, nd + N32);      // -> 1296
    stepX6R1(S.Sa, S.envbot, nd + N33);       // env_bot 1296
    normalize1296(S.envbot, S.red);           // range-keeper

    // ============ Row 2 (center row, j=0,1) ============
    insert_step(S.envtop, S.Sa, nd + N20);    // -> 7776
    cstep_full_tt(S.Sa, S.Sb, nd + N21);      // S1 in Sb

    // ============ E step: thread-per-k, FFMA2 over r ============
    // E[k*36 + d2*6 + r2] = sum_d3 envbot[d0,d1,d2,d3] * n23[u3,d3,r2], k=u3*36+d0*6+d1
    {
        const int t = threadIdx.x;
        if (t < 216) {
            const int u3 = t / 36, d0 = (t / 6) % 6, d1 = t % 6;
            float eb[36];
            const float4* p = reinterpret_cast<const float4*>(S.envbot + d0 * 216 + d1 * 36);
            #pragma unroll
            for (int q = 0; q < 9; ++q) { float4 v = p[q]; eb[q*4]=v.x; eb[q*4+1]=v.y; eb[q*4+2]=v.z; eb[q*4+3]=v.w; }
            u64 n2[18];
            const ulonglong2* np = reinterpret_cast<const ulonglong2*>(nd + N23 + u3 * 36);
            #pragma unroll
            for (int q = 0; q < 9; ++q) { ulonglong2 v = np[q]; n2[q*2] = v.x; n2[q*2+1] = v.y; }
            u64 acc[18];
            #pragma unroll
            for (int i = 0; i < 18; ++i) acc[i] = 0ull;
            #pragma unroll
            for (int d3 = 0; d3 < 6; ++d3)
                #pragma unroll
                for (int d2 = 0; d2 < 6; ++d2) {
                    const u64 e2 = pk2(eb[d2*6+d3], eb[d2*6+d3]);
                    #pragma unroll
                    for (int rp = 0; rp < 3; ++rp) fma2(acc[d2*3+rp], e2, n2[d3*3+rp]);
                }
            u64* op = reinterpret_cast<u64*>(S.Sa + t * 36);
            #pragma unroll
            for (int i = 0; i < 18; ++i) op[i] = acc[i];
        }
        __syncthreads();
    }

    // ============ W step: thread-per-(u,d,r), FFMA2 over l, 2k-unrolled ------
    // W[u*216 + r*36 + d*6 + l] = sum_k S1[u*1296 + k*6 + l] * E[k*36 + d*6 + r]
    {
        const int t = threadIdx.x;
        if (t < 216) {
            const int u = t / 36, d = (t / 6) % 6, r = t % 6;
            u64 acc0 = 0ull, acc1 = 0ull, acc2v = 0ull;
            const ulonglong2* sp = reinterpret_cast<const ulonglong2*>(S.Sb + u * 1296);
            const float* ep = S.Sa + d * 6 + r;
            #pragma unroll 4
            for (int kk = 0; kk < 108; ++kk) {      // 2 k per iter: 48B s1 = 3 LDS.128
                const ulonglong2 q0 = sp[kk*3], q1 = sp[kk*3+1], q2 = sp[kk*3+2];
                const float e0 = ep[kk * 72];
                const float e1 = ep[kk * 72 + 36];
                const u64 e02 = pk2(e0, e0);
                const u64 e12 = pk2(e1, e1);
                fma2(acc0, q0.x, e02); fma2(acc1, q0.y, e02); fma2(acc2v, q1.x, e02);
                fma2(acc0, q1.y, e12); fma2(acc1, q2.x, e12); fma2(acc2v, q2.y, e12);
            }
            u64* op = reinterpret_cast<u64*>(S.envtop + u * 216 + r * 36 + d * 6);
            op[0] = acc0; op[1] = acc1; op[2] = acc2v;
        }
        __syncthreads();
    }

    // ============ final: out[o] ∝ sum_p x_p * <Tc[p,o,:], W> ============
    {
        const int w = threadIdx.x >> 5, lane = threadIdx.x & 31;
        const float4* wv = reinterpret_cast<const float4*>(S.envtop);
        for (int po = w; po < 20; po += 8) {
            const float4* tc = reinterpret_cast<const float4*>(pc + (size_t)po * 1296);
            float s = 0.f;
            for (int g = lane; g < 324; g += 32) {
                float4 a = __ldg(tc + g), v = wv[g];
                s = fmaf(a.x, v.x, s); s = fmaf(a.y, v.y, s);
                s = fmaf(a.z, v.z, s); s = fmaf(a.w, v.w, s);
            }
            #pragma unroll
            for (int o = 16; o; o >>= 1) s += __shfl_xor_sync(0xffffffffu, s, o);
            if (lane == 0) S.dots[po] = s;
        }
        __syncthreads();
        if (threadIdx.x == 0) {
            const float x0 = xs[(2 * 4 + 2) * 2 + 0];
            const float x1 = xs[(2 * 4 + 2) * 2 + 1];
            float raw[10];
            float m = 0.f;
            #pragma unroll
            for (int o = 0; o < 10; ++o) {
                raw[o] = fmaf(x0, S.dots[o], x1 * S.dots[10 + o]);
                m = fmaxf(m, fabsf(raw[o]));
            }
            const float im = 1.0f / m;
            float ss = 0.f;
            #pragma unroll
            for (int o = 0; o < 10; ++o) { const float v = raw[o] * im; ss += v * v; }
            const float inv = rsqrtf(ss) * im;
            #pragma unroll
            for (int o = 0; o < 10; ++o) out[b * 10 + o] = raw[o] * inv;
        }
    }
}

extern "C" void kernel_launch(void* const* d_in, const int* in_sizes, int n_in,
                              void* d_out, int out_size) {
    const float *inp = nullptr, *peps = nullptr, *pc = nullptr;
    for (int i = 0; i < n_in; ++i) {
        if (in_sizes[i] == 1024 * 4 * 4 * 2)      inp  = (const float*)d_in[i];
        else if (in_sizes[i] == 4 * 4 * 2 * 1296) peps = (const float*)d_in[i];
        else if (in_sizes[i] == 2 * 10 * 1296)    pc   = (const float*)d_in[i];
    }
    const int smem = (int)sizeof(Smem);
    cudaFuncSetAttribute(peps_kernel, cudaFuncAttributeMaxDynamicSharedMemorySize, smem);
    peps_kernel<<<1024, NT, smem>>>(inp, peps, pc, (float*)d_out);
}

// round 12
// speedup vs baseline: 1.0154x; 1.0154x over previous
#include <cuda_runtime.h>

#define NT 256
typedef unsigned long long u64;

// X=Y=4, D=6, F_IN=2, F_OUT=10, CX=CY=2, B=1024
// inputs: (1024,4,4,2)  peps: (4,4,2,6,6,6,6)  peps_center: (2,10,6,6,6,6)
// out: (1024,10) float32
//
// All _unit() normalizations are positive per-batch scalars feeding a
// multilinear network -> cancel under final row-normalization. Keep 3
// (row0 env, env_top, env_bot) as fp32 range-keepers + max-scale the final
// 10-vector.
//
// Occupancy plan: 70.9KB smem/block, <=85 regs -> 3 blocks/SM.
// Node tensors built one-at-a-time into a single smem buffer, with the next
// node's LDGs register-staged during the current step (latency hidden).

// ---------------- f32x2 packed-math helpers ----------------
static __device__ __forceinline__ u64 pk2(float a, float b) {
    u64 r; asm("mov.b64 %0,{%1,%2};" : "=l"(r) : "f"(a), "f"(b)); return r;
}
static __device__ __forceinline__ void fma2(u64& d, u64 a, u64 b) {
    asm("fma.rn.f32x2 %0,%1,%2,%0;" : "+l"(d) : "l"(a), "l"(b));
}

struct Smem {
    float Sa[7776];     // also: red overlay Sa[0..7] at norm points (Sa dead there)
    float Sb[7776];     // Sb[6480..7776) doubles as envtop
    float node[1296];   // single node buffer; node[0..19] doubles as dots at end
    float envbot[1296]; // later reused as W output
};

// ---------------- block reduction / normalize ----------------
__device__ __forceinline__ float block_reduce(float v, float* red) {
    #pragma unroll
    for (int o = 16; o; o >>= 1) v += __shfl_xor_sync(0xffffffffu, v, o);
    int w = threadIdx.x >> 5;
    if ((threadIdx.x & 31) == 0) red[w] = v;
    __syncthreads();
    float r;
    if (threadIdx.x < 32) {
        r = (threadIdx.x < 8) ? red[threadIdx.x] : 0.f;
        #pragma unroll
        for (int o = 4; o; o >>= 1) r += __shfl_xor_sync(0xffffffffu, r, o);
        if (threadIdx.x == 0) red[0] = r;
    }
    __syncthreads();
    r = red[0];
    __syncthreads();
    return r;
}

__device__ __forceinline__ void normalize1296(float* buf, float* red) {
    float4* b4 = reinterpret_cast<float4*>(buf);
    float ss = 0.f;
    for (int i = threadIdx.x; i < 324; i += NT) {
        float4 v = b4[i];
        ss += v.x * v.x + v.y * v.y + v.z * v.z + v.w * v.w;
    }
    ss = block_reduce(ss, red);
    float inv = rsqrtf(ss);
    for (int i = threadIdx.x; i < 324; i += NT) {
        float4 v = b4[i];
        b4[i] = make_float4(v.x * inv, v.y * inv, v.z * inv, v.w * inv);
    }
    __syncthreads();
}

// ---------------- register-staged node loaders ----------------
// Standard packed layout: buf[((u*R+r)*Dd+d)*L+l], sliced axes fixed at 0.
template <int I, int J, int U, int R, int Dd, int L>
struct NodeLoad {
    static constexpr int N = U * R * Dd * L;
    static constexpr int Q = (N + NT - 1) / NT;
    float v[Q];
    __device__ __forceinline__ void load(const float* __restrict__ peps,
                                         const float* __restrict__ xs) {
        const float x0 = xs[(I * 4 + J) * 2 + 0];
        const float x1 = xs[(I * 4 + J) * 2 + 1];
        const float* T0 = peps + (size_t)((I * 4 + J) * 2) * 1296;
        const float* T1 = T0 + 1296;
        #pragma unroll
        for (int q = 0; q < Q; ++q) {
            int idx = threadIdx.x + q * NT;
            if (idx < N) {
                int l = idx % L;
                int t = idx / L;
                int d = t % Dd; t /= Dd;
                int r = t % R;
                int u = t / R;
                int g = ((u * 6 + r) * 6 + d) * 6 + l;
                v[q] = fmaf(x0, __ldg(T0 + g), x1 * __ldg(T1 + g));
            }
        }
    }
    __device__ __forceinline__ void store(float* __restrict__ buf) {
        #pragma unroll
        for (int q = 0; q < Q; ++q) {
            int idx = threadIdx.x + q * NT;
            if (idx < N) buf[idx] = v[q];
        }
    }
};

// Full node in transposed layout TT[u*216 + d*36 + l*6 + r] = Node[u][r][d][l]
template <int I, int J>
struct NodeLoadTT {
    float v[6];
    __device__ __forceinline__ void load(const float* __restrict__ peps,
                                         const float* __restrict__ xs) {
        const float x0 = xs[(I * 4 + J) * 2 + 0];
        const float x1 = xs[(I * 4 + J) * 2 + 1];
        const float* T0 = peps + (size_t)((I * 4 + J) * 2) * 1296;
        const float* T1 = T0 + 1296;
        #pragma unroll
        for (int q = 0; q < 6; ++q) {
            int g = threadIdx.x + q * NT;
            if (g < 1296) v[q] = fmaf(x0, __ldg(T0 + g), x1 * __ldg(T1 + g));
        }
    }
    __device__ __forceinline__ void store(float* __restrict__ buf) {
        #pragma unroll
        for (int q = 0; q < 6; ++q) {
            int g = threadIdx.x + q * NT;
            if (g < 1296) {
                int l = g % 6, d = (g / 6) % 6, r = (g / 36) % 6, u = g / 216;
                buf[u * 216 + d * 36 + l * 6 + r] = v[q];
            }
        }
    }
};

// ---------------- contraction steps ----------------

// M=6, U=1: out[t] = sum_x Sin[m*6+x] * T[a*SA + r*SR + x], t=m*36+a*6+r
template <int SA, int SR>
__device__ __forceinline__ void step6(const float* __restrict__ Sin,
                                      float* __restrict__ Sout,
                                      const float* __restrict__ T) {
    const int t = threadIdx.x;
    if (t < 216) {
        const int m = t / 36, a = (t / 6) % 6, r = t % 6;
        const float* sp = Sin + m * 6;
        const float* tp = T + a * SA + r * SR;
        float acc = 0.f;
        #pragma unroll
        for (int x = 0; x < 6; ++x) acc = fmaf(sp[x], tp[x], acc);
        Sout[t] = acc;
    }
    __syncthreads();
}

// M=36, U=1: thread=(m,a), 6 r outputs at Sout + t*6
template <int SA, int SR>
__device__ __forceinline__ void step36(const float* __restrict__ Sin,
                                       float* __restrict__ Sout,
                                       const float* __restrict__ T) {
    const int t = threadIdx.x;
    if (t < 216) {
        const int m = t / 6, a = t % 6;
        float sv[6];
        const float2* sp = reinterpret_cast<const float2*>(Sin + m * 6);
        #pragma unroll
        for (int q = 0; q < 3; ++q) { float2 v = sp[q]; sv[q*2] = v.x; sv[q*2+1] = v.y; }
        float acc[6];
        #pragma unroll
        for (int r = 0; r < 6; ++r) {
            const float2* tp = reinterpret_cast<const float2*>(T + a * SA + r * SR);
            float s = 0.f;
            #pragma unroll
            for (int q = 0; q < 3; ++q) {
                float2 v = tp[q];
                s = fmaf(sv[q*2], v.x, s); s = fmaf(sv[q*2+1], v.y, s);
            }
            acc[r] = s;
        }
        float2* op = reinterpret_cast<float2*>(Sout + t * 6);
        #pragma unroll
        for (int q = 0; q < 3; ++q) op[q] = make_float2(acc[q*2], acc[q*2+1]);
    }
    __syncthreads();
}

// M=216, X=6, R=1: out[m*6+a] = sum_x Sin[m*6+x]*T[a*6+x]
__device__ __forceinline__ void stepX6R1(const float* __restrict__ Sin,
                                         float* __restrict__ Sout,
                                         const float* __restrict__ T) {
    const int m = threadIdx.x;
    if (m < 216) {
        float sv[6];
        const float2* sp = reinterpret_cast<const float2*>(Sin + m * 6);
        #pragma unroll
        for (int q = 0; q < 3; ++q) { float2 v = sp[q]; sv[q*2] = v.x; sv[q*2+1] = v.y; }
        float tt[36];
        const float4* p = reinterpret_cast<const float4*>(T);
        #pragma unroll
        for (int q = 0; q < 9; ++q) { float4 v = p[q]; tt[q*4]=v.x; tt[q*4+1]=v.y; tt[q*4+2]=v.z; tt[q*4+3]=v.w; }
        float acc[6];
        #pragma unroll
        for (int a = 0; a < 6; ++a) {
            float s = 0.f;
            #pragma unroll
            for (int x = 0; x < 6; ++x) s = fmaf(sv[x], tt[a*6+x], s);
            acc[a] = s;
        }
        float2* op = reinterpret_cast<float2*>(Sout + m * 6);
        #pragma unroll
        for (int q = 0; q < 3; ++q) op[q] = make_float2(acc[q*2], acc[q*2+1]);
    }
    __syncthreads();
}

// X=1 insert (N10/N20): out[m*36+a*6+r] = sum_u Sin[u*216+m]*T[u*36+r*6+a]
// low-reg version: tt consumed in float4 chunks
__device__ __forceinline__ void insert_step(const float* __restrict__ Sin,
                                            float* __restrict__ Sout,
                                            const float* __restrict__ T) {
    const int m = threadIdx.x;
    if (m < 216) {
        float acc[36];
        #pragma unroll
        for (int i = 0; i < 36; ++i) acc[i] = 0.f;
        #pragma unroll
        for (int u = 0; u < 6; ++u) {
            const float s = Sin[u * 216 + m];
            const float4* p = reinterpret_cast<const float4*>(T + u * 36);  // broadcast
            #pragma unroll
            for (int q = 0; q < 9; ++q) {
                float4 v = p[q];
                // element e = q*4+j has (r = e/6, a = e%6); acc[a*6+r] += s*v
                #pragma unroll
                for (int j = 0; j < 4; ++j) {
                    const int e = q * 4 + j;
                    const int r = e / 6, a = e % 6;
                    const float val = (j == 0) ? v.x : (j == 1) ? v.y : (j == 2) ? v.z : v.w;
                    acc[a * 6 + r] = fmaf(s, val, acc[a * 6 + r]);
                }
            }
        }
        float4* op = reinterpret_cast<float4*>(Sout + m * 36);
        #pragma unroll
        for (int q = 0; q < 9; ++q) op[q] = make_float4(acc[q*4], acc[q*4+1], acc[q*4+2], acc[q*4+3]);
    }
    __syncthreads();
}

// N13-type: out[m*6+a] = sum_{u,x} Sin[(u*216+m)*6+x] * T[u*36+a*6+x]
__device__ __forceinline__ void contract_u_step(const float* __restrict__ Sin,
                                                float* __restrict__ Sout,
                                                const float* __restrict__ T) {
    const int m = threadIdx.x;
    if (m < 216) {
        float acc[6] = {0.f, 0.f, 0.f, 0.f, 0.f, 0.f};
        #pragma unroll
        for (int u = 0; u < 6; ++u) {
            float sv[6];
            const float2* sp = reinterpret_cast<const float2*>(Sin + (u * 216 + m) * 6);
            #pragma unroll
            for (int q = 0; q < 3; ++q) { float2 v = sp[q]; sv[q*2] = v.x; sv[q*2+1] = v.y; }
            #pragma unroll
            for (int a = 0; a < 6; ++a) {
                const float2* tp = reinterpret_cast<const float2*>(T + u * 36 + a * 6);
                float s = acc[a];
                #pragma unroll
                for (int q = 0; q < 3; ++q) {
                    float2 v = tp[q];
                    s = fmaf(sv[q*2], v.x, s); s = fmaf(sv[q*2+1], v.y, s);
                }
                acc[a] = s;
            }
        }
        float2* op = reinterpret_cast<float2*>(Sout + m * 6);
        #pragma unroll
        for (int q = 0; q < 3; ++q) op[q] = make_float2(acc[q*2], acc[q*2+1]);
    }
    __syncthreads();
}

// hot step, TT node, FFMA2 over packed r, low register pressure:
// out[mg*216+mi*36+a*6+r] = sum_{u,x} Sin[u*1296+(mg*6+mi)*6+x] * TT[u*216+a*36+x*6+r]
__device__ __forceinline__ void cstep_full_tt(const float* __restrict__ Sin,
                                              float* __restrict__ Sout,
                                              const float* __restrict__ TT) {
    const int t = threadIdx.x;
    if (t < 216) {
        const int mg = t / 6, a = t % 6;
        u64 acc[18];
        #pragma unroll
        for (int i = 0; i < 18; ++i) acc[i] = 0ull;
        #pragma unroll
        for (int u = 0; u < 6; ++u) {
            const float* sb = Sin + u * 1296 + mg * 36;
            const ulonglong2* tb = reinterpret_cast<const ulonglong2*>(TT + u * 216 + a * 36);
            #pragma unroll
            for (int xp = 0; xp < 3; ++xp) {
                // tt rows for x=2xp (even) and 2xp+1 (odd): 12 floats = 3 LDS.128
                ulonglong2 w0 = tb[xp*3], w1 = tb[xp*3+1], w2 = tb[xp*3+2];
                const u64 te0 = w0.x, te1 = w0.y, te2 = w1.x;   // x even, r-pairs
                const u64 to0 = w1.y, to1 = w2.x, to2 = w2.y;   // x odd
                #pragma unroll
                for (int mi = 0; mi < 6; ++mi) {
                    const float2 sv = *reinterpret_cast<const float2*>(sb + mi * 6 + xp * 2);
                    const u64 s0 = pk2(sv.x, sv.x);
                    const u64 s1 = pk2(sv.y, sv.y);
                    fma2(acc[mi*3+0], s0, te0); fma2(acc[mi*3+1], s0, te1); fma2(acc[mi*3+2], s0, te2);
                    fma2(acc[mi*3+0], s1, to0); fma2(acc[mi*3+1], s1, to1); fma2(acc[mi*3+2], s1, to2);
                }
            }
        }
        float* ob = Sout + mg * 216 + a * 6;
        #pragma unroll
        for (int mi = 0; mi < 6; ++mi) {
            u64* op = reinterpret_cast<u64*>(ob + mi * 36);
            op[0] = acc[mi*3]; op[1] = acc[mi*3+1]; op[2] = acc[mi*3+2];
        }
    }
    __syncthreads();
}

__global__ void __launch_bounds__(NT, 3)
peps_kernel(const float* __restrict__ inp, const float* __restrict__ peps,
            const float* __restrict__ pc, float* __restrict__ out) {
    extern __shared__ __align__(16) char smem_raw[];
    Smem& S = *reinterpret_cast<Smem*>(smem_raw);
    const int b = blockIdx.x;
    const float* xs = inp + b * 32;
    float* const ENVTOP = S.Sb + 6480;   // overlay in Sb tail
    float* const RED = S.Sa;             // Sa dead at every norm point
    float* const DOTS = S.node;          // node dead at final

    // ---- prefetch N01; inline N00 -> Sa (36 elems) ----
    NodeLoad<0, 1, 1, 6, 6, 6> st01; st01.load(peps, xs);
    if (threadIdx.x < 36) {
        const int d = threadIdx.x / 6, r = threadIdx.x % 6;
        const int g = (r * 6 + d) * 6;
        const float* T0 = peps + (size_t)0 * 1296;
        const float* T1 = T0 + 1296;
        S.Sa[threadIdx.x] = fmaf(xs[0], __ldg(T0 + g), xs[1] * __ldg(T1 + g));
    }
    __syncthreads();

    // ============ Row 0 ============
    st01.store(S.node); NodeLoad<0, 2, 1, 6, 6, 6> st02; st02.load(peps, xs); __syncthreads();
    step6<6, 36>(S.Sa, S.Sb, S.node);                 // -> 216
    st02.store(S.node); NodeLoad<0, 3, 1, 1, 6, 6> st03; st03.load(peps, xs); __syncthreads();
    step36<6, 36>(S.Sb, S.Sa, S.node);                // -> 1296
    st03.store(S.node); NodeLoad<1, 0, 6, 6, 6, 1> st10; st10.load(peps, xs); __syncthreads();
    stepX6R1(S.Sa, S.Sb, S.node);                     // -> 1296 in Sb
    st10.store(S.node); NodeLoadTT<1, 1> st11; st11.load(peps, xs); __syncthreads();
    normalize1296(S.Sb, RED);                         // range-keeper

    // ============ Row 1 ============
    insert_step(S.Sb, S.Sa, S.node);                  // N10 -> 7776
    st11.store(S.node); NodeLoadTT<1, 2> st12; st12.load(peps, xs); __syncthreads();
    cstep_full_tt(S.Sa, S.Sb, S.node);                // N11
    st12.store(S.node); NodeLoad<1, 3, 6, 1, 6, 6> st13; st13.load(peps, xs); __syncthreads();
    cstep_full_tt(S.Sb, S.Sa, S.node);                // N12
    st13.store(S.node); NodeLoad<3, 1, 6, 6, 1, 6> st31; st31.load(peps, xs); __syncthreads();
    contract_u_step(S.Sa, ENVTOP, S.node);            // N13 -> env_top (Sb tail)
    normalize1296(ENVTOP, RED);                       // range-keeper

    // ---- inline N30 -> Sa[0:36] ----
    if (threadIdx.x < 36) {
        const int g = threadIdx.x * 36;               // (u*6+r)*36
        const float* T0 = peps + (size_t)((3 * 4 + 0) * 2) * 1296;
        const float* T1 = T0 + 1296;
        S.Sa[threadIdx.x] = fmaf(xs[(3 * 4 + 0) * 2], __ldg(T0 + g),
                                 xs[(3 * 4 + 0) * 2 + 1] * __ldg(T1 + g));
    }
    __syncthreads();

    // ============ Row 3 ============
    st31.store(S.node); NodeLoad<3, 2, 6, 6, 1, 6> st32; st32.load(peps, xs); __syncthreads();
    step6<36, 6>(S.Sa, S.Sb, S.node);                 // N31 -> 216
    st32.store(S.node); NodeLoad<3, 3, 6, 1, 1, 6> st33; st33.load(peps, xs); __syncthreads();
    step36<36, 6>(S.Sb, S.Sa, S.node);                // N32 -> 1296
    st33.store(S.node); NodeLoad<2, 0, 6, 6, 6, 1> st20; st20.load(peps, xs); __syncthreads();
    stepX6R1(S.Sa, S.envbot, S.node);                 // N33 -> env_bot
    st20.store(S.node); NodeLoadTT<2, 1> st21; st21.load(peps, xs); __syncthreads();
    normalize1296(S.envbot, RED);                     // range-keeper

    // ============ Row 2 (j=0,1) ============
    insert_step(ENVTOP, S.Sa, S.node);                // N20 -> 7776
    st21.store(S.node); NodeLoad<2, 3, 6, 1, 6, 6> st23; st23.load(peps, xs); __syncthreads();
    cstep_full_tt(S.Sa, S.Sb, S.node);                // N21 -> S1 in Sb
    st23.store(S.node); __syncthreads();

    // ============ E step: thread-per-k, FFMA2 over r, low-reg ============
    // E[k*36 + d2*6 + r2] = sum_d3 envbot[d0,d1,d2,d3]*n23[u3,d3,r2], k=u3*36+d0*6+d1
    {
        const int t = threadIdx.x;
        if (t < 216) {
            const int u3 = t / 36, d0 = (t / 6) % 6, d1 = t % 6;
            u64 acc[18];
            #pragma unroll
            for (int i = 0; i < 18; ++i) acc[i] = 0ull;
            #pragma unroll
            for (int d3 = 0; d3 < 6; ++d3) {
                const u64* np = reinterpret_cast<const u64*>(S.node + u3 * 36 + d3 * 6);
                const u64 n0 = np[0], n1 = np[1], n2v = np[2];
                const float* ebp = S.envbot + d0 * 216 + d1 * 36 + d3;
                #pragma unroll
                for (int d2 = 0; d2 < 6; ++d2) {
                    const float e = ebp[d2 * 6];
                    const u64 e2 = pk2(e, e);
                    fma2(acc[d2*3+0], e2, n0); fma2(acc[d2*3+1], e2, n1); fma2(acc[d2*3+2], e2, n2v);
                }
            }
            u64* op = reinterpret_cast<u64*>(S.Sa + t * 36);
            #pragma unroll
            for (int i = 0; i < 18; ++i) op[i] = acc[i];
        }
        __syncthreads();
    }

    // ============ W step: thread-per-(u,d,r), FFMA2 over l ============
    // W[u*216+r*36+d*6+l] = sum_k S1[u*1296+k*6+l] * E[k*36+d*6+r]  -> envbot
    {
        const int t = threadIdx.x;
        if (t < 216) {
            const int u = t / 36, d = (t / 6) % 6, r = t % 6;
            u64 acc0 = 0ull, acc1 = 0ull, acc2v = 0ull;
            const ulonglong2* sp = reinterpret_cast<const ulonglong2*>(S.Sb + u * 1296);
            const float* ep = S.Sa + d * 6 + r;
            #pragma unroll 4
            for (int kk = 0; kk < 108; ++kk) {
                const ulonglong2 q0 = sp[kk*3], q1 = sp[kk*3+1], q2 = sp[kk*3+2];
                const u64 e02 = pk2(ep[kk * 72], ep[kk * 72]);
                const u64 e12 = pk2(ep[kk * 72 + 36], ep[kk * 72 + 36]);
                fma2(acc0, q0.x, e02); fma2(acc1, q0.y, e02); fma2(acc2v, q1.x, e02);
                fma2(acc0, q1.y, e12); fma2(acc1, q2.x, e12); fma2(acc2v, q2.y, e12);
            }
            u64* op = reinterpret_cast<u64*>(S.envbot + u * 216 + r * 36 + d * 6);
            op[0] = acc0; op[1] = acc1; op[2] = acc2v;
        }
        __syncthreads();
    }

    // ============ final: out[o] ∝ sum_p x_p * <Tc[p,o,:], W> ============
    {
        const int w = threadIdx.x >> 5, lane = threadIdx.x & 31;
        const float4* wv = reinterpret_cast<const float4*>(S.envbot);
        for (int po = w; po < 20; po += 8) {
            const float4* tc = reinterpret_cast<const float4*>(pc + (size_t)po * 1296);
            float s = 0.f;
            for (int g = lane; g < 324; g += 32) {
                float4 a = __ldg(tc + g), v = wv[g];
                s = fmaf(a.x, v.x, s); s = fmaf(a.y, v.y, s);
                s = fmaf(a.z, v.z, s); s = fmaf(a.w, v.w, s);
            }
            #pragma unroll
            for (int o = 16; o; o >>= 1) s += __shfl_xor_sync(0xffffffffu, s, o);
            if (lane == 0) DOTS[po] = s;
        }
        __syncthreads();
        if (threadIdx.x == 0) {
            const float x0 = xs[(2 * 4 + 2) * 2 + 0];
            const float x1 = xs[(2 * 4 + 2) * 2 + 1];
            float raw[10];
            float m = 0.f;
            #pragma unroll
            for (int o = 0; o < 10; ++o) {
                raw[o] = fmaf(x0, DOTS[o], x1 * DOTS[10 + o]);
                m = fmaxf(m, fabsf(raw[o]));
            }
            const float im = 1.0f / m;
            float ss = 0.f;
            #pragma unroll
            for (int o = 0; o < 10; ++o) { const float v = raw[o] * im; ss += v * v; }
            const float inv = rsqrtf(ss) * im;
            #pragma unroll
            for (int o = 0; o < 10; ++o) out[b * 10 + o] = raw[o] * inv;
        }
    }
}

extern "C" void kernel_launch(void* const* d_in, const int* in_sizes, int n_in,
                              void* d_out, int out_size) {
    const float *inp = nullptr, *peps = nullptr, *pc = nullptr;
    for (int i = 0; i < n_in; ++i) {
        if (in_sizes[i] == 1024 * 4 * 4 * 2)      inp  = (const float*)d_in[i];
        else if (in_sizes[i] == 4 * 4 * 2 * 1296) peps = (const float*)d_in[i];
        else if (in_sizes[i] == 2 * 10 * 1296)    pc   = (const float*)d_in[i];
    }
    const int smem = (int)sizeof(Smem);   // 72,576 B -> 3 blocks/SM
    cudaFuncSetAttribute(peps_kernel, cudaFuncAttributeMaxDynamicSharedMemorySize, smem);
    peps_kernel<<<1024, NT, smem>>>(inp, peps, pc, (float*)d_out);
}

// round 14
// speedup vs baseline: 1.0495x; 1.0336x over previous
#include <cuda_runtime.h>

#define NT 256
typedef unsigned long long u64;

// X=Y=4, D=6, F_IN=2, F_OUT=10, CX=CY=2, B=1024
// inputs: (1024,4,4,2)  peps: (4,4,2,6,6,6,6)  peps_center: (2,10,6,6,6,6)
// out: (1024,10) float32
//
// All _unit() normalizations cancel under the final row-normalization
// (positive per-batch scalars on a multilinear network). Three range-keepers
// remain, implemented as: accumulate ss in the producing step, reduce via a
// DEDICATED smem scratch (never aliased -> no warp-async race), and fold
// rsqrt(ss) into the NEXT 216-float node tensor. Row-0 and row-3 boundary
// chains are independent and identically shaped -> fused dual steps.

// ---------------- f32x2 packed-math helpers ----------------
static __device__ __forceinline__ u64 pk2(float a, float b) {
    u64 r; asm("mov.b64 %0,{%1,%2};" : "=l"(r) : "f"(a), "f"(b)); return r;
}
static __device__ __forceinline__ void fma2(u64& d, u64 a, u64 b) {
    asm("fma.rn.f32x2 %0,%1,%2,%0;" : "+l"(d) : "l"(a), "l"(b));
}

struct Smem {
    float Sa[7776];     // ping
    float Sb[7776];     // pong; Sb[6480..7776) doubles as envtop
    float node[1296];   // node buffer; [0:216)=A slot, [648:864)=B slot; dots at end
    float envbot[1296]; // later reused as W output
    float red[16];      // DEDICATED reduction scratch (fixes R13 race)
};

// ---------------- dual block reduction (dedicated scratch) ----------------
__device__ __forceinline__ float2 block_reduce2(float a, float b, float* red) {
    #pragma unroll
    for (int o = 16; o; o >>= 1) {
        a += __shfl_xor_sync(0xffffffffu, a, o);
        b += __shfl_xor_sync(0xffffffffu, b, o);
    }
    const int w = threadIdx.x >> 5;
    if ((threadIdx.x & 31) == 0) { red[w] = a; red[8 + w] = b; }
    __syncthreads();
    if (threadIdx.x < 32) {
        float ra = (threadIdx.x < 8) ? red[threadIdx.x] : 0.f;
        float rb = (threadIdx.x < 8) ? red[8 + threadIdx.x] : 0.f;
        #pragma unroll
        for (int o = 4; o; o >>= 1) {
            ra += __shfl_xor_sync(0xffffffffu, ra, o);
            rb += __shfl_xor_sync(0xffffffffu, rb, o);
        }
        if (threadIdx.x == 0) { red[0] = ra; red[1] = rb; }
    }
    __syncthreads();
    return make_float2(red[0], red[1]);
}

// ---------------- register-staged node loaders ----------------
template <int I, int J, int U, int R, int Dd, int L>
struct NodeLoad {
    static constexpr int N = U * R * Dd * L;
    static constexpr int Q = (N + NT - 1) / NT;
    float v[Q];
    __device__ __forceinline__ void load(const float* __restrict__ peps,
                                         const float* __restrict__ xs) {
        const float x0 = xs[(I * 4 + J) * 2 + 0];
        const float x1 = xs[(I * 4 + J) * 2 + 1];
        const float* T0 = peps + (size_t)((I * 4 + J) * 2) * 1296;
        const float* T1 = T0 + 1296;
        #pragma unroll
        for (int q = 0; q < Q; ++q) {
            int idx = threadIdx.x + q * NT;
            if (idx < N) {
                int l = idx % L;
                int t = idx / L;
                int d = t % Dd; t /= Dd;
                int r = t % R;
                int u = t / R;
                int g = ((u * 6 + r) * 6 + d) * 6 + l;
                v[q] = fmaf(x0, __ldg(T0 + g), x1 * __ldg(T1 + g));
            }
        }
    }
    __device__ __forceinline__ void store(float* __restrict__ buf) {
        #pragma unroll
        for (int q = 0; q < Q; ++q) {
            int idx = threadIdx.x + q * NT;
            if (idx < N) buf[idx] = v[q];
        }
    }
    __device__ __forceinline__ void store_scaled(float* __restrict__ buf, float s) {
        #pragma unroll
        for (int q = 0; q < Q; ++q) {
            int idx = threadIdx.x + q * NT;
            if (idx < N) buf[idx] = v[q] * s;
        }
    }
};

// Full node in transposed layout TT[u*216 + d*36 + l*6 + r] = Node[u][r][d][l]
template <int I, int J>
struct NodeLoadTT {
    float v[6];
    __device__ __forceinline__ void load(const float* __restrict__ peps,
                                         const float* __restrict__ xs) {
        const float x0 = xs[(I * 4 + J) * 2 + 0];
        const float x1 = xs[(I * 4 + J) * 2 + 1];
        const float* T0 = peps + (size_t)((I * 4 + J) * 2) * 1296;
        const float* T1 = T0 + 1296;
        #pragma unroll
        for (int q = 0; q < 6; ++q) {
            int g = threadIdx.x + q * NT;
            if (g < 1296) v[q] = fmaf(x0, __ldg(T0 + g), x1 * __ldg(T1 + g));
        }
    }
    __device__ __forceinline__ void store(float* __restrict__ buf) {
        #pragma unroll
        for (int q = 0; q < 6; ++q) {
            int g = threadIdx.x + q * NT;
            if (g < 1296) {
                int l = g % 6, d = (g / 6) % 6, r = (g / 36) % 6, u = g / 216;
                buf[u * 216 + d * 36 + l * 6 + r] = v[q];
            }
        }
    }
};

// ---------------- step bodies (NO internal sync) ----------------

template <int SA, int SR>
__device__ __forceinline__ void step6_body(const float* __restrict__ Sin,
                                           float* __restrict__ Sout,
                                           const float* __restrict__ T) {
    const int t = threadIdx.x;
    if (t < 216) {
        const int m = t / 36, a = (t / 6) % 6, r = t % 6;
        const float* sp = Sin + m * 6;
        const float* tp = T + a * SA + r * SR;
        float acc = 0.f;
        #pragma unroll
        for (int x = 0; x < 6; ++x) acc = fmaf(sp[x], tp[x], acc);
        Sout[t] = acc;
    }
}

template <int SA, int SR>
__device__ __forceinline__ void step36_body(const float* __restrict__ Sin,
                                            float* __restrict__ Sout,
                                            const float* __restrict__ T) {
    const int t = threadIdx.x;
    if (t < 216) {
        const int m = t / 6, a = t % 6;
        float sv[6];
        const float2* sp = reinterpret_cast<const float2*>(Sin + m * 6);
        #pragma unroll
        for (int q = 0; q < 3; ++q) { float2 v = sp[q]; sv[q*2] = v.x; sv[q*2+1] = v.y; }
        float acc[6];
        #pragma unroll
        for (int r = 0; r < 6; ++r) {
            const float2* tp = reinterpret_cast<const float2*>(T + a * SA + r * SR);
            float s = 0.f;
            #pragma unroll
            for (int q = 0; q < 3; ++q) {
                float2 v = tp[q];
                s = fmaf(sv[q*2], v.x, s); s = fmaf(sv[q*2+1], v.y, s);
            }
            acc[r] = s;
        }
        float2* op = reinterpret_cast<float2*>(Sout + t * 6);
        #pragma unroll
        for (int q = 0; q < 3; ++q) op[q] = make_float2(acc[q*2], acc[q*2+1]);
    }
}

__device__ __forceinline__ float stepX6R1_body(const float* __restrict__ Sin,
                                               float* __restrict__ Sout,
                                               const float* __restrict__ T) {
    const int m = threadIdx.x;
    float ss = 0.f;
    if (m < 216) {
        float sv[6];
        const float2* sp = reinterpret_cast<const float2*>(Sin + m * 6);
        #pragma unroll
        for (int q = 0; q < 3; ++q) { float2 v = sp[q]; sv[q*2] = v.x; sv[q*2+1] = v.y; }
        float tt[36];
        const float4* p = reinterpret_cast<const float4*>(T);
        #pragma unroll
        for (int q = 0; q < 9; ++q) { float4 v = p[q]; tt[q*4]=v.x; tt[q*4+1]=v.y; tt[q*4+2]=v.z; tt[q*4+3]=v.w; }
        float acc[6];
        #pragma unroll
        for (int a = 0; a < 6; ++a) {
            float s = 0.f;
            #pragma unroll
            for (int x = 0; x < 6; ++x) s = fmaf(sv[x], tt[a*6+x], s);
            acc[a] = s;
            ss = fmaf(s, s, ss);
        }
        float2* op = reinterpret_cast<float2*>(Sout + m * 6);
        #pragma unroll
        for (int q = 0; q < 3; ++q) op[q] = make_float2(acc[q*2], acc[q*2+1]);
    }
    return ss;
}

__device__ __forceinline__ void insert_body(const float* __restrict__ Sin,
                                            float* __restrict__ Sout,
                                            const float* __restrict__ T) {
    const int m = threadIdx.x;
    if (m < 216) {
        float acc[36];
        #pragma unroll
        for (int i = 0; i < 36; ++i) acc[i] = 0.f;
        #pragma unroll
        for (int u = 0; u < 6; ++u) {
            const float s = Sin[u * 216 + m];
            const float4* p = reinterpret_cast<const float4*>(T + u * 36);
            #pragma unroll
            for (int q = 0; q < 9; ++q) {
                float4 v = p[q];
                #pragma unroll
                for (int j = 0; j < 4; ++j) {
                    const int e = q * 4 + j;
                    const int r = e / 6, a = e % 6;
                    const float val = (j == 0) ? v.x : (j == 1) ? v.y : (j == 2) ? v.z : v.w;
                    acc[a * 6 + r] = fmaf(s, val, acc[a * 6 + r]);
                }
            }
        }
        float4* op = reinterpret_cast<float4*>(Sout + m * 36);
        #pragma unroll
        for (int q = 0; q < 9; ++q) op[q] = make_float4(acc[q*4], acc[q*4+1], acc[q*4+2], acc[q*4+3]);
    }
}

__device__ __forceinline__ float contract_u_body(const float* __restrict__ Sin,
                                                 float* __restrict__ Sout,
                                                 const float* __restrict__ T) {
    const int m = threadIdx.x;
    float ss = 0.f;
    if (m < 216) {
        float acc[6] = {0.f, 0.f, 0.f, 0.f, 0.f, 0.f};
        #pragma unroll
        for (int u = 0; u < 6; ++u) {
            float sv[6];
            const float2* sp = reinterpret_cast<const float2*>(Sin + (u * 216 + m) * 6);
            #pragma unroll
            for (int q = 0; q < 3; ++q) { float2 v = sp[q]; sv[q*2] = v.x; sv[q*2+1] = v.y; }
            #pragma unroll
            for (int a = 0; a < 6; ++a) {
                const float2* tp = reinterpret_cast<const float2*>(T + u * 36 + a * 6);
                float s = acc[a];
                #pragma unroll
                for (int q = 0; q < 3; ++q) {
                    float2 v = tp[q];
                    s = fmaf(sv[q*2], v.x, s); s = fmaf(sv[q*2+1], v.y, s);
                }
                acc[a] = s;
            }
        }
        #pragma unroll
        for (int a = 0; a < 6; ++a) ss = fmaf(acc[a], acc[a], ss);
        float2* op = reinterpret_cast<float2*>(Sout + m * 6);
        #pragma unroll
        for (int q = 0; q < 3; ++q) op[q] = make_float2(acc[q*2], acc[q*2+1]);
    }
    return ss;
}

__device__ __forceinline__ void cstep_full_tt_body(const float* __restrict__ Sin,
                                                   float* __restrict__ Sout,
                                                   const float* __restrict__ TT) {
    const int t = threadIdx.x;
    if (t < 216) {
        const int mg = t / 6, a = t % 6;
        u64 acc[18];
        #pragma unroll
        for (int i = 0; i < 18; ++i) acc[i] = 0ull;
        #pragma unroll
        for (int u = 0; u < 6; ++u) {
            const float* sb = Sin + u * 1296 + mg * 36;
            const ulonglong2* tb = reinterpret_cast<const ulonglong2*>(TT + u * 216 + a * 36);
            #pragma unroll
            for (int xp = 0; xp < 3; ++xp) {
                ulonglong2 w0 = tb[xp*3], w1 = tb[xp*3+1], w2 = tb[xp*3+2];
                const u64 te0 = w0.x, te1 = w0.y, te2 = w1.x;
                const u64 to0 = w1.y, to1 = w2.x, to2 = w2.y;
                #pragma unroll
                for (int mi = 0; mi < 6; ++mi) {
                    const float2 sv = *reinterpret_cast<const float2*>(sb + mi * 6 + xp * 2);
                    const u64 s0 = pk2(sv.x, sv.x);
                    const u64 s1 = pk2(sv.y, sv.y);
                    fma2(acc[mi*3+0], s0, te0); fma2(acc[mi*3+1], s0, te1); fma2(acc[mi*3+2], s0, te2);
                    fma2(acc[mi*3+0], s1, to0); fma2(acc[mi*3+1], s1, to1); fma2(acc[mi*3+2], s1, to2);
                }
            }
        }
        float* ob = Sout + mg * 216 + a * 6;
        #pragma unroll
        for (int mi = 0; mi < 6; ++mi) {
            u64* op = reinterpret_cast<u64*>(ob + mi * 36);
            op[0] = acc[mi*3]; op[1] = acc[mi*3+1]; op[2] = acc[mi*3+2];
        }
    }
}

__global__ void __launch_bounds__(NT, 3)
peps_kernel(const float* __restrict__ inp, const float* __restrict__ peps,
            const float* __restrict__ pc, float* __restrict__ out) {
    extern __shared__ __align__(16) char smem_raw[];
    Smem& S = *reinterpret_cast<Smem*>(smem_raw);
    const int b = blockIdx.x;
    const float* xs = inp + b * 32;
    float* const ENVTOP = S.Sb + 6480;
    float* const NA = S.node;         // slot A
    float* const NB = S.node + 648;   // slot B
    float* const DOTS = S.node;       // dead at final
    float* const RED = S.red;         // dedicated, never aliased

    // ---- prefetch N01,N31; inline N00 -> Sa[0:36], N30 -> Sa[3888:3924] ----
    NodeLoad<0, 1, 1, 6, 6, 6> stA; stA.load(peps, xs);
    NodeLoad<3, 1, 6, 6, 1, 6> stB; stB.load(peps, xs);
    if (threadIdx.x < 36) {
        const int d = threadIdx.x / 6, r = threadIdx.x % 6;
        const int g = (r * 6 + d) * 6;
        const float* T0 = peps;
        const float* T1 = T0 + 1296;
        S.Sa[threadIdx.x] = fmaf(xs[0], __ldg(T0 + g), xs[1] * __ldg(T1 + g));
    } else if (threadIdx.x >= 64 && threadIdx.x < 100) {
        const int tt = threadIdx.x - 64;
        const int g = tt * 36;                      // (u*6+r)*36
        const float* T0 = peps + (size_t)24 * 1296; // (3,0) pair
        const float* T1 = T0 + 1296;
        S.Sa[3888 + tt] = fmaf(xs[24], __ldg(T0 + g), xs[25] * __ldg(T1 + g));
    }
    __syncthreads();

    // ============ fused row0 + row3 boundary chains ============
    stA.store(NA); stB.store(NB);
    NodeLoad<0, 2, 1, 6, 6, 6> stA2; stA2.load(peps, xs);
    NodeLoad<3, 2, 6, 6, 1, 6> stB2; stB2.load(peps, xs);
    __syncthreads();
    step6_body<6, 36>(S.Sa, S.Sb, NA);               // row0 -> Sb[0:216]
    step6_body<36, 6>(S.Sa + 3888, S.Sb + 3888, NB); // row3 -> Sb[3888:4104]
    __syncthreads();
    stA2.store(NA); stB2.store(NB);
    NodeLoad<0, 3, 1, 1, 6, 6> stA3; stA3.load(peps, xs);
    NodeLoad<3, 3, 6, 1, 1, 6> stB3; stB3.load(peps, xs);
    __syncthreads();
    step36_body<6, 36>(S.Sb, S.Sa, NA);
    step36_body<36, 6>(S.Sb + 3888, S.Sa + 3888, NB);
    __syncthreads();
    stA3.store(NA); stB3.store(NB);
    NodeLoad<1, 0, 6, 6, 6, 1> st10; st10.load(peps, xs);
    __syncthreads();
    float ss0 = stepX6R1_body(S.Sa, S.Sb, NA);           // row0 env -> Sb[0:1296]
    float ss3 = stepX6R1_body(S.Sa + 3888, S.envbot, NB);// env_bot -> envbot
    const float2 iv = block_reduce2(ss0, ss3, RED);
    const float inv0 = rsqrtf(iv.x);
    const float inv3 = rsqrtf(iv.y);

    // ============ Row 1 ============
    st10.store_scaled(NA, inv0);                         // range-keeper folded in
    NodeLoadTT<1, 1> st11; st11.load(peps, xs);
    __syncthreads();
    insert_body(S.Sb, S.Sa, NA);                         // -> 7776
    __syncthreads();
    st11.store(S.node);
    NodeLoadTT<1, 2> st12; st12.load(peps, xs);
    __syncthreads();
    cstep_full_tt_body(S.Sa, S.Sb, S.node);              // N11
    __syncthreads();
    st12.store(S.node);
    NodeLoad<1, 3, 6, 1, 6, 6> st13; st13.load(peps, xs);
    __syncthreads();
    cstep_full_tt_body(S.Sb, S.Sa, S.node);              // N12
    __syncthreads();
    st13.store(NA);
    NodeLoad<2, 0, 6, 6, 6, 1> st20; st20.load(peps, xs);
    __syncthreads();
    float sst = contract_u_body(S.Sa, ENVTOP, NA);       // env_top (Sb tail)
    const float2 ivt = block_reduce2(sst, 0.f, RED);
    const float inv_top = rsqrtf(ivt.x);

    // ============ Row 2 (j=0,1) ============
    st20.store_scaled(NA, inv_top);                      // range-keeper folded in
    NodeLoadTT<2, 1> st21; st21.load(peps, xs);
    __syncthreads();
    insert_body(ENVTOP, S.Sa, NA);                       // -> 7776
    __syncthreads();
    st21.store(S.node);
    NodeLoad<2, 3, 6, 1, 6, 6> st23; st23.load(peps, xs);
    __syncthreads();
    cstep_full_tt_body(S.Sa, S.Sb, S.node);              // N21 -> S1 in Sb
    __syncthreads();
    st23.store_scaled(NA, inv3);                         // N23, range-keeper folded
    __syncthreads();

    // ============ E step: thread-per-k, FFMA2 over r ============
    // E[k*36 + d2*6 + r2] = sum_d3 envbot[d0,d1,d2,d3]*n23[u3,d3,r2], k=u3*36+d0*6+d1
    {
        const int t = threadIdx.x;
        if (t < 216) {
            const int u3 = t / 36, d0 = (t / 6) % 6, d1 = t % 6;
            u64 acc[18];
            #pragma unroll
            for (int i = 0; i < 18; ++i) acc[i] = 0ull;
            #pragma unroll
            for (int d3 = 0; d3 < 6; ++d3) {
                const u64* np = reinterpret_cast<const u64*>(NA + u3 * 36 + d3 * 6);
                const u64 n0 = np[0], n1 = np[1], n2v = np[2];
                const float* ebp = S.envbot + d0 * 216 + d1 * 36 + d3;
                #pragma unroll
                for (int d2 = 0; d2 < 6; ++d2) {
                    const float e = ebp[d2 * 6];
                    const u64 e2 = pk2(e, e);
                    fma2(acc[d2*3+0], e2, n0); fma2(acc[d2*3+1], e2, n1); fma2(acc[d2*3+2], e2, n2v);
                }
            }
            u64* op = reinterpret_cast<u64*>(S.Sa + t * 36);
            #pragma unroll
            for (int i = 0; i < 18; ++i) op[i] = acc[i];
        }
        __syncthreads();
    }

    // ============ W step: thread-per-(u,d,r), FFMA2 over l ============
    // W[u*216+r*36+d*6+l] = sum_k S1[u*1296+k*6+l] * E[k*36+d*6+r]  -> envbot
    {
        const int t = threadIdx.x;
        if (t < 216) {
            const int u = t / 36, d = (t / 6) % 6, r = t % 6;
            u64 acc0 = 0ull, acc1 = 0ull, acc2v = 0ull;
            const ulonglong2* sp = reinterpret_cast<const ulonglong2*>(S.Sb + u * 1296);
            const float* ep = S.Sa + d * 6 + r;
            #pragma unroll 4
            for (int kk = 0; kk < 108; ++kk) {
                const ulonglong2 q0 = sp[kk*3], q1 = sp[kk*3+1], q2 = sp[kk*3+2];
                const u64 e02 = pk2(ep[kk * 72], ep[kk * 72]);
                const u64 e12 = pk2(ep[kk * 72 + 36], ep[kk * 72 + 36]);
                fma2(acc0, q0.x, e02); fma2(acc1, q0.y, e02); fma2(acc2v, q1.x, e02);
                fma2(acc0, q1.y, e12); fma2(acc1, q2.x, e12); fma2(acc2v, q2.y, e12);
            }
            u64* op = reinterpret_cast<u64*>(S.envbot + u * 216 + r * 36 + d * 6);
            op[0] = acc0; op[1] = acc1; op[2] = acc2v;
        }
        __syncthreads();
    }

    // ============ final: out[o] ∝ sum_p x_p * <Tc[p,o,:], W> ============
    {
        const int w = threadIdx.x >> 5, lane = threadIdx.x & 31;
        const float4* wv = reinterpret_cast<const float4*>(S.envbot);
        for (int po = w; po < 20; po += 8) {
            const float4* tc = reinterpret_cast<const float4*>(pc + (size_t)po * 1296);
            float s = 0.f;
            for (int g = lane; g < 324; g += 32) {
                float4 a = __ldg(tc + g), v = wv[g];
                s = fmaf(a.x, v.x, s); s = fmaf(a.y, v.y, s);
                s = fmaf(a.z, v.z, s); s = fmaf(a.w, v.w, s);
            }
            #pragma unroll
            for (int o = 16; o; o >>= 1) s += __shfl_xor_sync(0xffffffffu, s, o);
            if (lane == 0) DOTS[po] = s;
        }
        __syncthreads();
        if (threadIdx.x == 0) {
            const float x0 = xs[(2 * 4 + 2) * 2 + 0];
            const float x1 = xs[(2 * 4 + 2) * 2 + 1];
            float raw[10];
            float m = 0.f;
            #pragma unroll
            for (int o = 0; o < 10; ++o) {
                raw[o] = fmaf(x0, DOTS[o], x1 * DOTS[10 + o]);
                m = fmaxf(m, fabsf(raw[o]));
            }
            const float im = 1.0f / m;
            float ss = 0.f;
            #pragma unroll
            for (int o = 0; o < 10; ++o) { const float v = raw[o] * im; ss += v * v; }
            const float inv = rsqrtf(ss) * im;
            #pragma unroll
            for (int o = 0; o < 10; ++o) out[b * 10 + o] = raw[o] * inv;
        }
    }
}

extern "C" void kernel_launch(void* const* d_in, const int* in_sizes, int n_in,
                              void* d_out, int out_size) {
    const float *inp = nullptr, *peps = nullptr, *pc = nullptr;
    for (int i = 0; i < n_in; ++i) {
        if (in_sizes[i] == 1024 * 4 * 4 * 2)      inp  = (const float*)d_in[i];
        else if (in_sizes[i] == 4 * 4 * 2 * 1296) peps = (const float*)d_in[i];
        else if (in_sizes[i] == 2 * 10 * 1296)    pc   = (const float*)d_in[i];
    }
    const int smem = (int)sizeof(Smem);   // 72,640 B -> 3 blocks/SM
    cudaFuncSetAttribute(peps_kernel, cudaFuncAttributeMaxDynamicSharedMemorySize, smem);
    peps_kernel<<<1024, NT, smem>>>(inp, peps, pc, (float*)d_out);
}